// round 11
// baseline (speedup 1.0000x reference)
#include <cuda_runtime.h>
#include <cuda_bf16.h>
#include <cstdint>

// Problem constants (fixed by the reference)
#define T_TABLES 13
#define L_VALS   131072
#define B_BAGS   4096
#define N_ROWS   100000
#define D_DIM    128

// One warp per (table, bag). Lane l owns float4 #l of the 128-float row.
// Each gathered row = one coalesced 512B warp transaction (4x128B lines).
// Unroll x8 with independent accumulators -> MLP=8 outstanding row loads,
// which also shortens the serial tail of oversized bags (~270 rows max).
__global__ __launch_bounds__(512) void embbag_warp_per_bag(
    const int*   __restrict__ values,   // [T, L]
    const int*   __restrict__ offsets,  // [T, B]
    const float* __restrict__ weights,  // [T, N, D]
    float*       __restrict__ out)      // [B, T, D]
{
    const int lane = threadIdx.x & 31;
    const int wib  = threadIdx.x >> 5;                     // warp in block (0..15)
    const int t    = blockIdx.y;                           // table
    const int b    = blockIdx.x * (blockDim.x >> 5) + wib; // bag
    if (b >= B_BAGS) return;

    const int* offs = offsets + t * B_BAGS;
    const int start = __ldg(offs + b);
    const int end   = (b == B_BAGS - 1) ? L_VALS : __ldg(offs + b + 1);

    const int* vals = values + (size_t)t * L_VALS;
    const float4* wt = reinterpret_cast<const float4*>(
        weights + (size_t)t * N_ROWS * D_DIM);

    float4 a0 = make_float4(0.f, 0.f, 0.f, 0.f);
    float4 a1 = make_float4(0.f, 0.f, 0.f, 0.f);
    float4 a2 = make_float4(0.f, 0.f, 0.f, 0.f);
    float4 a3 = make_float4(0.f, 0.f, 0.f, 0.f);

    int i = start;
    // Main loop: 8 independent gathers in flight per warp.
    for (; i + 8 <= end; i += 8) {
        int v[8];
        #pragma unroll
        for (int k = 0; k < 8; ++k) v[k] = __ldg(vals + i + k);
        float4 w[8];
        #pragma unroll
        for (int k = 0; k < 8; ++k) w[k] = __ldg(wt + (size_t)v[k] * 32 + lane);
        a0.x += w[0].x + w[4].x; a0.y += w[0].y + w[4].y;
        a0.z += w[0].z + w[4].z; a0.w += w[0].w + w[4].w;
        a1.x += w[1].x + w[5].x; a1.y += w[1].y + w[5].y;
        a1.z += w[1].z + w[5].z; a1.w += w[1].w + w[5].w;
        a2.x += w[2].x + w[6].x; a2.y += w[2].y + w[6].y;
        a2.z += w[2].z + w[6].z; a2.w += w[2].w + w[6].w;
        a3.x += w[3].x + w[7].x; a3.y += w[3].y + w[7].y;
        a3.z += w[3].z + w[7].z; a3.w += w[3].w + w[7].w;
    }
    // Remainder (0..7 rows).
    for (; i < end; ++i) {
        const int v = __ldg(vals + i);
        const float4 w = __ldg(wt + (size_t)v * 32 + lane);
        a0.x += w.x; a0.y += w.y; a0.z += w.z; a0.w += w.w;
    }

    float4 r;
    r.x = (a0.x + a1.x) + (a2.x + a3.x);
    r.y = (a0.y + a1.y) + (a2.y + a3.y);
    r.z = (a0.z + a1.z) + (a2.z + a3.z);
    r.w = (a0.w + a1.w) + (a2.w + a3.w);

    // out[b][t][:] — write even for empty bags (d_out is poisoned to 0xAA).
    float4* op = reinterpret_cast<float4*>(
        out + ((size_t)b * T_TABLES + t) * D_DIM);
    op[lane] = r;
}

extern "C" void kernel_launch(void* const* d_in, const int* in_sizes, int n_in,
                              void* d_out, int out_size)
{
    const int*   values  = (const int*)d_in[0];   // [T, L] int32
    const int*   offsets = (const int*)d_in[1];   // [T, B] int32
    const float* weights = (const float*)d_in[2]; // [T, N, D] float32
    float*       out     = (float*)d_out;         // [B, T, D] float32

    (void)in_sizes; (void)n_in; (void)out_size;

    dim3 block(512);                         // 16 warps = 16 bags per block
    dim3 grid((B_BAGS + 15) / 16, T_TABLES); // x fastest -> table-local L2 reuse
    embbag_warp_per_bag<<<grid, block>>>(values, offsets, weights, out);
}

// round 12
// speedup vs baseline: 1.1538x; 1.1538x over previous
#include <cuda_runtime.h>
#include <cuda_bf16.h>
#include <cstdint>

// Problem constants (fixed by the reference)
#define T_TABLES 13
#define L_VALS   131072
#define B_BAGS   4096
#define N_ROWS   100000
#define D_DIM    128

// Two warps per (table, bag): warp-half h in {0,1} owns floats [h*64, h*64+64).
// Lane l owns float2 #(h*32+l) -> each gathered row-half = one coalesced 256B
// warp transaction. Lower register use (~32) -> 8 CTAs/SM (100% occupancy),
// 2x warp count (106K) halves the imbalance tail, MLP=8 per warp.
__global__ __launch_bounds__(256) void embbag_halfrow_per_warp(
    const int*   __restrict__ values,   // [T, L]
    const int*   __restrict__ offsets,  // [T, B]
    const float* __restrict__ weights,  // [T, N, D]
    float*       __restrict__ out)      // [B, T, D]
{
    const int lane = threadIdx.x & 31;
    const int wib  = threadIdx.x >> 5;                 // warp in block (0..7)
    const int gw   = blockIdx.x * 8 + wib;             // global warp within table
    const int b    = gw >> 1;                          // bag
    const int h    = gw & 1;                           // row half (0 or 1)
    const int t    = blockIdx.y;                       // table
    if (b >= B_BAGS) return;

    const int* offs = offsets + t * B_BAGS;
    const int start = __ldg(offs + b);
    const int end   = (b == B_BAGS - 1) ? L_VALS : __ldg(offs + b + 1);

    const int* vals = values + (size_t)t * L_VALS;
    // Weight table viewed as float2; row = 64 float2. This warp reads
    // float2 elements [h*32 + lane] of each row.
    const float2* wt = reinterpret_cast<const float2*>(
        weights + (size_t)t * N_ROWS * D_DIM);
    const int fofs = h * 32 + lane;                    // float2 offset in row

    float2 a0 = make_float2(0.f, 0.f);
    float2 a1 = make_float2(0.f, 0.f);
    float2 a2 = make_float2(0.f, 0.f);
    float2 a3 = make_float2(0.f, 0.f);

    int i = start;
    // Main loop: 8 independent 256B gathers in flight per warp.
    for (; i + 8 <= end; i += 8) {
        int v[8];
        #pragma unroll
        for (int k = 0; k < 8; ++k) v[k] = __ldg(vals + i + k);
        float2 w[8];
        #pragma unroll
        for (int k = 0; k < 8; ++k)
            w[k] = __ldg(wt + (size_t)v[k] * 64 + fofs);
        a0.x += w[0].x + w[4].x;  a0.y += w[0].y + w[4].y;
        a1.x += w[1].x + w[5].x;  a1.y += w[1].y + w[5].y;
        a2.x += w[2].x + w[6].x;  a2.y += w[2].y + w[6].y;
        a3.x += w[3].x + w[7].x;  a3.y += w[3].y + w[7].y;
    }
    // Remainder (0..7 rows).
    for (; i < end; ++i) {
        const int v = __ldg(vals + i);
        const float2 w = __ldg(wt + (size_t)v * 64 + fofs);
        a0.x += w.x; a0.y += w.y;
    }

    float2 r;
    r.x = (a0.x + a1.x) + (a2.x + a3.x);
    r.y = (a0.y + a1.y) + (a2.y + a3.y);

    // out[b][t][h*64 + lane*2 .. +1] — write even for empty bags
    // (d_out is poisoned to 0xAA).
    float2* op = reinterpret_cast<float2*>(
        out + ((size_t)b * T_TABLES + t) * D_DIM);
    op[fofs] = r;
}

extern "C" void kernel_launch(void* const* d_in, const int* in_sizes, int n_in,
                              void* d_out, int out_size)
{
    const int*   values  = (const int*)d_in[0];   // [T, L] int32
    const int*   offsets = (const int*)d_in[1];   // [T, B] int32
    const float* weights = (const float*)d_in[2]; // [T, N, D] float32
    float*       out     = (float*)d_out;         // [B, T, D] float32

    (void)in_sizes; (void)n_in; (void)out_size;

    // 8 warps/block; 2 warps per bag -> 4 bags/block; 2*4096 warps per table.
    dim3 block(256);
    dim3 grid((B_BAGS * 2 + 7) / 8, T_TABLES); // x fastest -> table-local L2 reuse
    embbag_halfrow_per_warp<<<grid, block>>>(values, offsets, weights, out);
}

// round 13
// speedup vs baseline: 1.7207x; 1.4913x over previous
#include <cuda_runtime.h>
#include <cuda_bf16.h>
#include <cstdint>

// Problem constants (fixed by the reference)
#define T_TABLES 13
#define L_VALS   131072
#define B_BAGS   4096
#define N_ROWS   100000
#define D_DIM    128

// Two warps per (table, bag): warp-half h in {0,1} owns floats [h*64, h*64+64).
// Lane l owns float2 #(h*32+l) -> each gathered row-half = one coalesced 256B
// warp transaction.
//
// __launch_bounds__(256, 4): cap 4 CTAs/SM -> up to 64 regs/thread. This is
// deliberate: at the default target ptxas allocated 38 regs and RECYCLED the
// w[0..7] registers, serializing the 8-load batch (MLP_eff < 1, DRAM stuck at
// 36%). With 64 regs all 8 load chains keep distinct registers -> true MLP=8.
__global__ __launch_bounds__(256, 4) void embbag_halfrow_per_warp(
    const int*   __restrict__ values,   // [T, L]
    const int*   __restrict__ offsets,  // [T, B]
    const float* __restrict__ weights,  // [T, N, D]
    float*       __restrict__ out)      // [B, T, D]
{
    const int lane = threadIdx.x & 31;
    const int wib  = threadIdx.x >> 5;                 // warp in block (0..7)
    const int gw   = blockIdx.x * 8 + wib;             // global warp within table
    const int b    = gw >> 1;                          // bag
    const int h    = gw & 1;                           // row half (0 or 1)
    const int t    = blockIdx.y;                       // table
    if (b >= B_BAGS) return;

    const int* offs = offsets + t * B_BAGS;
    const int start = __ldg(offs + b);
    const int end   = (b == B_BAGS - 1) ? L_VALS : __ldg(offs + b + 1);

    const int* vals = values + (size_t)t * L_VALS;
    // Weight table viewed as float2; row = 64 float2. This warp reads
    // float2 elements [h*32 + lane] of each row.
    const float2* wt = reinterpret_cast<const float2*>(
        weights + (size_t)t * N_ROWS * D_DIM);
    const int fofs = h * 32 + lane;                    // float2 offset in row

    float2 a0 = make_float2(0.f, 0.f);
    float2 a1 = make_float2(0.f, 0.f);
    float2 a2 = make_float2(0.f, 0.f);
    float2 a3 = make_float2(0.f, 0.f);

    int i = start;
    // Main loop: 8 independent 256B gathers in flight per warp.
    for (; i + 8 <= end; i += 8) {
        int v[8];
        #pragma unroll
        for (int k = 0; k < 8; ++k) v[k] = __ldg(vals + i + k);
        float2 w[8];
        #pragma unroll
        for (int k = 0; k < 8; ++k)
            w[k] = __ldg(wt + (size_t)v[k] * 64 + fofs);
        a0.x += w[0].x + w[4].x;  a0.y += w[0].y + w[4].y;
        a1.x += w[1].x + w[5].x;  a1.y += w[1].y + w[5].y;
        a2.x += w[2].x + w[6].x;  a2.y += w[2].y + w[6].y;
        a3.x += w[3].x + w[7].x;  a3.y += w[3].y + w[7].y;
    }
    // Remainder (0..7 rows).
    for (; i < end; ++i) {
        const int v = __ldg(vals + i);
        const float2 w = __ldg(wt + (size_t)v * 64 + fofs);
        a0.x += w.x; a0.y += w.y;
    }

    float2 r;
    r.x = (a0.x + a1.x) + (a2.x + a3.x);
    r.y = (a0.y + a1.y) + (a2.y + a3.y);

    // out[b][t][h*64 + lane*2 .. +1] — write even for empty bags
    // (d_out is poisoned to 0xAA).
    float2* op = reinterpret_cast<float2*>(
        out + ((size_t)b * T_TABLES + t) * D_DIM);
    op[fofs] = r;
}

extern "C" void kernel_launch(void* const* d_in, const int* in_sizes, int n_in,
                              void* d_out, int out_size)
{
    const int*   values  = (const int*)d_in[0];   // [T, L] int32
    const int*   offsets = (const int*)d_in[1];   // [T, B] int32
    const float* weights = (const float*)d_in[2]; // [T, N, D] float32
    float*       out     = (float*)d_out;         // [B, T, D] float32

    (void)in_sizes; (void)n_in; (void)out_size;

    // 8 warps/block; 2 warps per bag -> 4 bags/block; 2*4096 warps per table.
    dim3 block(256);
    dim3 grid((B_BAGS * 2 + 7) / 8, T_TABLES); // x fastest -> table-local L2 reuse
    embbag_halfrow_per_warp<<<grid, block>>>(values, offsets, weights, out);
}